// round 7
// baseline (speedup 1.0000x reference)
#include <cuda_runtime.h>
#include <cstdint>
#include <cmath>

#define B_ 128
#define T_ 512
#define I_ 256
#define H_ 512

// ---- scratch (static device memory; no runtime allocation) ----
// g_xproj[g][t][b][h] : input projections + bias, fp32. 4*512*128*512 floats = 512MB.
__device__ float g_xproj[(size_t)4 * T_ * B_ * H_];
__device__ float g_h[2][B_ * H_];     // double-buffered hidden state
__device__ float g_c[B_ * H_];        // cell state
__device__ float g_hsum[B_ * H_];     // running sum of h over time

// ---- packed fp32x2 FMA (SASS FFMA2; 2x scalar FFMA throughput) ----
__device__ __forceinline__ void fma2(unsigned long long& d,
                                     unsigned long long a,
                                     unsigned long long b) {
    asm("fma.rn.f32x2 %0, %1, %2, %0;" : "+l"(d) : "l"(a), "l"(b));
}
__device__ __forceinline__ float lo32(unsigned long long v) {
    return __uint_as_float((unsigned)(v & 0xffffffffull));
}
__device__ __forceinline__ float hi32(unsigned long long v) {
    return __uint_as_float((unsigned)(v >> 32));
}
__device__ __forceinline__ float sigmoidf_(float x) {
    return 1.0f / (1.0f + expf(-x));
}

// ---------------------------------------------------------------------------
// init: zero h[0], c, hsum (must run every graph replay)
// ---------------------------------------------------------------------------
__global__ void lstm_init() {
    int i = blockIdx.x * blockDim.x + threadIdx.x;
    if (i < B_ * H_) {
        g_h[0][i] = 0.0f;
        g_c[i]    = 0.0f;
        g_hsum[i] = 0.0f;
    }
}

// ---------------------------------------------------------------------------
// projection GEMM: C[bt][g*512+h] = x[bt,:] . W_g[h,:] + b_g[h]
// tile 64(M=bt) x 64(N=gh) x K=256, 128 threads, micro 4Mx8N via f32x2.
// grid: (65536/64, 2048/64) = (1024, 32). Each N-block sits inside one gate.
// ---------------------------------------------------------------------------
__global__ __launch_bounds__(128) void lstm_proj(
    const float* __restrict__ x,
    const float* __restrict__ Wz, const float* __restrict__ Ws,
    const float* __restrict__ Wf, const float* __restrict__ Wo,
    const float* __restrict__ bz, const float* __restrict__ bs,
    const float* __restrict__ bf, const float* __restrict__ bo)
{
    __shared__ __align__(16) float2 As2[32][64];  // A (x) values pre-duplicated
    __shared__ __align__(16) float  Bs[32][64];   // W values, [k][n]

    const int tid = threadIdx.x;
    const int r0  = blockIdx.x * 64;     // bt rows
    const int n0  = blockIdx.y * 64;     // stacked gate*H columns
    const int g   = n0 >> 9;
    const int h0  = n0 & 511;

    const float* W    = (g == 0) ? Wz : (g == 1) ? Ws : (g == 2) ? Wf : Wo;
    const float* bias = (g == 0) ? bz : (g == 1) ? bs : (g == 2) ? bf : bo;

    const int tn = tid & 7;    // n micro index (n = tn*8)
    const int tm = tid >> 3;   // m micro index (m = tm*4), 0..15

    // loader role
    const int lm = tid & 63;
    const int qb = (tid >> 6) * 4;
    const float* xr = x + (size_t)(r0 + lm) * I_;
    const float* wr = W + (size_t)(h0 + lm) * I_;

    unsigned long long acc[4][4];
#pragma unroll
    for (int i = 0; i < 4; i++)
#pragma unroll
        for (int j = 0; j < 4; j++) acc[i][j] = 0ull;

    float4 pa[4], pw[4];
#pragma unroll
    for (int i = 0; i < 4; i++) {
        pa[i] = *(const float4*)(xr + (qb + i) * 4);
        pw[i] = *(const float4*)(wr + (qb + i) * 4);
    }

    for (int kt = 0; kt < I_ / 32; kt++) {
#pragma unroll
        for (int i = 0; i < 4; i++) {
            int q = qb + i;
            As2[q * 4 + 0][lm] = make_float2(pa[i].x, pa[i].x);
            As2[q * 4 + 1][lm] = make_float2(pa[i].y, pa[i].y);
            As2[q * 4 + 2][lm] = make_float2(pa[i].z, pa[i].z);
            As2[q * 4 + 3][lm] = make_float2(pa[i].w, pa[i].w);
            Bs[q * 4 + 0][lm] = pw[i].x;
            Bs[q * 4 + 1][lm] = pw[i].y;
            Bs[q * 4 + 2][lm] = pw[i].z;
            Bs[q * 4 + 3][lm] = pw[i].w;
        }
        __syncthreads();
        if (kt + 1 < I_ / 32) {   // prefetch next k-tile into registers
            int k0 = (kt + 1) * 32;
#pragma unroll
            for (int i = 0; i < 4; i++) {
                pa[i] = *(const float4*)(xr + k0 + (qb + i) * 4);
                pw[i] = *(const float4*)(wr + k0 + (qb + i) * 4);
            }
        }
#pragma unroll
        for (int kk = 0; kk < 32; kk++) {
            ulonglong2 a01 = *(const ulonglong2*)&As2[kk][tm * 4];
            ulonglong2 a23 = *(const ulonglong2*)&As2[kk][tm * 4 + 2];
            ulonglong2 b01 = *(const ulonglong2*)&Bs[kk][tn * 8];
            ulonglong2 b23 = *(const ulonglong2*)&Bs[kk][tn * 8 + 4];
            fma2(acc[0][0], a01.x, b01.x); fma2(acc[0][1], a01.x, b01.y);
            fma2(acc[0][2], a01.x, b23.x); fma2(acc[0][3], a01.x, b23.y);
            fma2(acc[1][0], a01.y, b01.x); fma2(acc[1][1], a01.y, b01.y);
            fma2(acc[1][2], a01.y, b23.x); fma2(acc[1][3], a01.y, b23.y);
            fma2(acc[2][0], a23.x, b01.x); fma2(acc[2][1], a23.x, b01.y);
            fma2(acc[2][2], a23.x, b23.x); fma2(acc[2][3], a23.x, b23.y);
            fma2(acc[3][0], a23.y, b01.x); fma2(acc[3][1], a23.y, b01.y);
            fma2(acc[3][2], a23.y, b23.x); fma2(acc[3][3], a23.y, b23.y);
        }
        __syncthreads();
    }

    // epilogue: +bias, write to g_xproj[g][t][b][h]
    float bv[8];
#pragma unroll
    for (int j = 0; j < 8; j++) bv[j] = bias[h0 + tn * 8 + j];
#pragma unroll
    for (int i = 0; i < 4; i++) {
        int r  = r0 + tm * 4 + i;
        int bb = r >> 9;          // T = 512
        int tt = r & 511;
        float* orow = g_xproj + (((size_t)g * T_ + tt) * B_ + bb) * H_ + h0 + tn * 8;
#pragma unroll
        for (int jp = 0; jp < 4; jp++) {
            float2 v = make_float2(lo32(acc[i][jp]) + bv[jp * 2],
                                   hi32(acc[i][jp]) + bv[jp * 2 + 1]);
            *(float2*)(orow + jp * 2) = v;
        }
    }
}

// ---------------------------------------------------------------------------
// fused LSTM step: all 4 gate GEMMs + nonlinearity + c/h update + h-sum.
// grid (4, 32): b-tile 32, h-tile 16. Per CTA: M=64 (4 gates x 16 h), N=32, K=512.
// 128 threads, micro 4Mx4N via f32x2. R streamed from L2, h from L2.
// ---------------------------------------------------------------------------
__global__ __launch_bounds__(128) void lstm_step(
    int t, int cur,
    const float* __restrict__ Rz, const float* __restrict__ Rs,
    const float* __restrict__ Rf, const float* __restrict__ Ro)
{
    __shared__ __align__(16) float2 R2[32][64];     // R values duplicated, [k][m]
    __shared__ __align__(16) float  Hsm[32][32];    // h_prev, [k][b]
    __shared__ __align__(16) float  xp[4][32][16];  // xproj tile [g][b][hr]
    __shared__ __align__(16) float  act[4][32][16]; // activations [g][b][hr]

    const int tid = threadIdx.x;
    const int b0  = blockIdx.x * 32;
    const int h0  = blockIdx.y * 16;

    const int tn = tid & 7;    // n = tn*4
    const int tm = tid >> 3;   // m = tm*4, 0..15

    const float* hprev = g_h[cur];

    // stage xproj tile (coalesced 64B rows) — consumed after the GEMM barriers
    {
#pragma unroll
        for (int j = 0; j < 4; j++) {
            int idx = j * 128 + tid;   // 0..511 float4s
            int row = idx >> 2;        // 0..127 = (g, bl)
            int q   = idx & 3;
            int gg  = row >> 5;
            int bl  = row & 31;
            const float* src = g_xproj +
                (((size_t)gg * T_ + t) * B_ + (b0 + bl)) * H_ + h0 + q * 4;
            *(float4*)&xp[gg][bl][q * 4] = *(const float4*)src;
        }
    }

    // loader roles
    const int lm  = tid & 63;            // R tile row (gate-stacked m)
    const int qb  = (tid >> 6) * 4;
    const int lg  = lm >> 4;
    const int lhr = lm & 15;
    const float* Rp =
        ((lg == 0) ? Rz : (lg == 1) ? Rs : (lg == 2) ? Rf : Ro) +
        (size_t)(h0 + lhr) * H_;
    const int hb = tid & 31;             // Hs tile row (batch)
    const int hq = tid >> 5;             // 0..3

    unsigned long long acc[4][2];
#pragma unroll
    for (int i = 0; i < 4; i++) { acc[i][0] = 0ull; acc[i][1] = 0ull; }

    float4 ra[4], rh[2];
#pragma unroll
    for (int i = 0; i < 4; i++) ra[i] = *(const float4*)(Rp + (qb + i) * 4);
#pragma unroll
    for (int j = 0; j < 2; j++) {
        int q = j * 4 + hq;
        rh[j] = *(const float4*)(hprev + (size_t)(b0 + hb) * H_ + q * 4);
    }

    for (int kt = 0; kt < 16; kt++) {
#pragma unroll
        for (int i = 0; i < 4; i++) {
            int q = qb + i;
            R2[q * 4 + 0][lm] = make_float2(ra[i].x, ra[i].x);
            R2[q * 4 + 1][lm] = make_float2(ra[i].y, ra[i].y);
            R2[q * 4 + 2][lm] = make_float2(ra[i].z, ra[i].z);
            R2[q * 4 + 3][lm] = make_float2(ra[i].w, ra[i].w);
        }
#pragma unroll
        for (int j = 0; j < 2; j++) {
            int q = j * 4 + hq;
            Hsm[q * 4 + 0][hb] = rh[j].x;
            Hsm[q * 4 + 1][hb] = rh[j].y;
            Hsm[q * 4 + 2][hb] = rh[j].z;
            Hsm[q * 4 + 3][hb] = rh[j].w;
        }
        __syncthreads();
        if (kt + 1 < 16) {   // prefetch next k-tile
            int k0 = (kt + 1) * 32;
#pragma unroll
            for (int i = 0; i < 4; i++)
                ra[i] = *(const float4*)(Rp + k0 + (qb + i) * 4);
#pragma unroll
            for (int j = 0; j < 2; j++) {
                int q = j * 4 + hq;
                rh[j] = *(const float4*)(hprev + (size_t)(b0 + hb) * H_ + k0 + q * 4);
            }
        }
#pragma unroll
        for (int kk = 0; kk < 32; kk++) {
            ulonglong2 a01 = *(const ulonglong2*)&R2[kk][tm * 4];
            ulonglong2 a23 = *(const ulonglong2*)&R2[kk][tm * 4 + 2];
            ulonglong2 bv  = *(const ulonglong2*)&Hsm[kk][tn * 4];
            fma2(acc[0][0], a01.x, bv.x); fma2(acc[0][1], a01.x, bv.y);
            fma2(acc[1][0], a01.y, bv.x); fma2(acc[1][1], a01.y, bv.y);
            fma2(acc[2][0], a23.x, bv.x); fma2(acc[2][1], a23.x, bv.y);
            fma2(acc[3][0], a23.y, bv.x); fma2(acc[3][1], a23.y, bv.y);
        }
        __syncthreads();
    }

    // epilogue: pre-activation -> nonlinearity -> act[g][b][hr]
    // (each warp handles exactly one gate -> uniform branch)
#pragma unroll
    for (int i = 0; i < 4; i++) {
        int m  = tm * 4 + i;
        int gg = m >> 4;
        int hr = m & 15;
#pragma unroll
        for (int jp = 0; jp < 2; jp++) {
            int nl = tn * 4 + jp * 2;
            float p0 = lo32(acc[i][jp]) + xp[gg][nl][hr];
            float p1 = hi32(acc[i][jp]) + xp[gg][nl + 1][hr];
            if (gg == 0) { p0 = tanhf(p0); p1 = tanhf(p1); }
            else         { p0 = sigmoidf_(p0); p1 = sigmoidf_(p1); }
            act[gg][nl][hr]     = p0;
            act[gg][nl + 1][hr] = p1;
        }
    }
    __syncthreads();

    // combine gates: c_new = s*z + f*c ; h_new = o*tanh(c_new); accumulate mean
    float* hnext = g_h[cur ^ 1];
#pragma unroll
    for (int j = 0; j < 4; j++) {
        int p  = j * 128 + tid;     // 0..511 = (bl, hr)
        int bl = p >> 4;
        int hr = p & 15;
        float z = act[0][bl][hr];
        float s = act[1][bl][hr];
        float f = act[2][bl][hr];
        float o = act[3][bl][hr];
        int   gi = (b0 + bl) * H_ + h0 + hr;
        float cnew = s * z + f * g_c[gi];
        g_c[gi] = cnew;
        float hn = o * tanhf(cnew);
        hnext[gi]  = hn;
        g_hsum[gi] += hn;
    }
}

// ---------------------------------------------------------------------------
__global__ void lstm_final(float* __restrict__ out) {
    int i = blockIdx.x * blockDim.x + threadIdx.x;
    if (i < B_ * H_) out[i] = g_hsum[i] * (1.0f / (float)T_);
}

// ---------------------------------------------------------------------------
extern "C" void kernel_launch(void* const* d_in, const int* in_sizes, int n_in,
                              void* d_out, int out_size) {
    const float* x  = (const float*)d_in[0];
    const float* Wz = (const float*)d_in[1];
    const float* Ws = (const float*)d_in[2];
    const float* Wf = (const float*)d_in[3];
    const float* Wo = (const float*)d_in[4];
    const float* Rz = (const float*)d_in[5];
    const float* Rs = (const float*)d_in[6];
    const float* Rf = (const float*)d_in[7];
    const float* Ro = (const float*)d_in[8];
    const float* bz = (const float*)d_in[9];
    const float* bs = (const float*)d_in[10];
    const float* bf = (const float*)d_in[11];
    const float* bo = (const float*)d_in[12];

    lstm_init<<<64, 1024>>>();
    lstm_proj<<<dim3((B_ * T_) / 64, (4 * H_) / 64), 128>>>(
        x, Wz, Ws, Wf, Wo, bz, bs, bf, bo);
    for (int t = 0; t < T_; t++)
        lstm_step<<<dim3(B_ / 32, H_ / 16), 128>>>(t, t & 1, Rz, Rs, Rf, Ro);
    lstm_final<<<64, 1024>>>((float*)d_out);
}

// round 8
// speedup vs baseline: 1.2559x; 1.2559x over previous
#include <cuda_runtime.h>
#include <cstdint>
#include <cmath>

#define B_ 128
#define T_ 512
#define I_ 256
#define H_ 512
#define NCTA 128

// ---- static device scratch ----
__device__ float g_xproj[(size_t)4 * T_ * B_ * H_];   // [g][t][b][h]
__device__ float g_h[2][B_ * H_];                     // double-buffered hidden state
__device__ unsigned g_count;                          // global barrier counter
__device__ unsigned g_sense;                          // global barrier generation

// ---- packed fp32x2 FMA ----
__device__ __forceinline__ void fma2(unsigned long long& d,
                                     unsigned long long a,
                                     unsigned long long b) {
    asm("fma.rn.f32x2 %0, %1, %2, %0;" : "+l"(d) : "l"(a), "l"(b));
}
__device__ __forceinline__ float lo32(unsigned long long v) {
    return __uint_as_float((unsigned)(v & 0xffffffffull));
}
__device__ __forceinline__ float hi32(unsigned long long v) {
    return __uint_as_float((unsigned)(v >> 32));
}
__device__ __forceinline__ unsigned long long dup32(unsigned x) {
    unsigned long long r;
    asm("mov.b64 %0, {%1, %1};" : "=l"(r) : "r"(x));
    return r;
}
__device__ __forceinline__ float sigmoidf_(float x) {
    return 1.0f / (1.0f + expf(-x));
}

// ---------------------------------------------------------------------------
__global__ void lstm_reset() {
    if (threadIdx.x == 0) { g_count = 0; g_sense = 0; }
}

// ---------------------------------------------------------------------------
// projection GEMM (unchanged from R6): C[bt][g*512+h] = x . W_g^T + b_g
// ---------------------------------------------------------------------------
__global__ __launch_bounds__(128) void lstm_proj(
    const float* __restrict__ x,
    const float* __restrict__ Wz, const float* __restrict__ Ws,
    const float* __restrict__ Wf, const float* __restrict__ Wo,
    const float* __restrict__ bz, const float* __restrict__ bs,
    const float* __restrict__ bf, const float* __restrict__ bo)
{
    __shared__ __align__(16) float2 As2[32][64];
    __shared__ __align__(16) float  Bs[32][64];

    const int tid = threadIdx.x;
    const int r0  = blockIdx.x * 64;
    const int n0  = blockIdx.y * 64;
    const int g   = n0 >> 9;
    const int h0  = n0 & 511;

    const float* W    = (g == 0) ? Wz : (g == 1) ? Ws : (g == 2) ? Wf : Wo;
    const float* bias = (g == 0) ? bz : (g == 1) ? bs : (g == 2) ? bf : bo;

    const int tn = tid & 7;
    const int tm = tid >> 3;

    const int lm = tid & 63;
    const int qb = (tid >> 6) * 4;
    const float* xr = x + (size_t)(r0 + lm) * I_;
    const float* wr = W + (size_t)(h0 + lm) * I_;

    unsigned long long acc[4][4];
#pragma unroll
    for (int i = 0; i < 4; i++)
#pragma unroll
        for (int j = 0; j < 4; j++) acc[i][j] = 0ull;

    float4 pa[4], pw[4];
#pragma unroll
    for (int i = 0; i < 4; i++) {
        pa[i] = *(const float4*)(xr + (qb + i) * 4);
        pw[i] = *(const float4*)(wr + (qb + i) * 4);
    }

    for (int kt = 0; kt < I_ / 32; kt++) {
#pragma unroll
        for (int i = 0; i < 4; i++) {
            int q = qb + i;
            As2[q * 4 + 0][lm] = make_float2(pa[i].x, pa[i].x);
            As2[q * 4 + 1][lm] = make_float2(pa[i].y, pa[i].y);
            As2[q * 4 + 2][lm] = make_float2(pa[i].z, pa[i].z);
            As2[q * 4 + 3][lm] = make_float2(pa[i].w, pa[i].w);
            Bs[q * 4 + 0][lm] = pw[i].x;
            Bs[q * 4 + 1][lm] = pw[i].y;
            Bs[q * 4 + 2][lm] = pw[i].z;
            Bs[q * 4 + 3][lm] = pw[i].w;
        }
        __syncthreads();
        if (kt + 1 < I_ / 32) {
            int k0 = (kt + 1) * 32;
#pragma unroll
            for (int i = 0; i < 4; i++) {
                pa[i] = *(const float4*)(xr + k0 + (qb + i) * 4);
                pw[i] = *(const float4*)(wr + k0 + (qb + i) * 4);
            }
        }
#pragma unroll
        for (int kk = 0; kk < 32; kk++) {
            ulonglong2 a01 = *(const ulonglong2*)&As2[kk][tm * 4];
            ulonglong2 a23 = *(const ulonglong2*)&As2[kk][tm * 4 + 2];
            ulonglong2 b01 = *(const ulonglong2*)&Bs[kk][tn * 8];
            ulonglong2 b23 = *(const ulonglong2*)&Bs[kk][tn * 8 + 4];
            fma2(acc[0][0], a01.x, b01.x); fma2(acc[0][1], a01.x, b01.y);
            fma2(acc[0][2], a01.x, b23.x); fma2(acc[0][3], a01.x, b23.y);
            fma2(acc[1][0], a01.y, b01.x); fma2(acc[1][1], a01.y, b01.y);
            fma2(acc[1][2], a01.y, b23.x); fma2(acc[1][3], a01.y, b23.y);
            fma2(acc[2][0], a23.x, b01.x); fma2(acc[2][1], a23.x, b01.y);
            fma2(acc[2][2], a23.x, b23.x); fma2(acc[2][3], a23.x, b23.y);
            fma2(acc[3][0], a23.y, b01.x); fma2(acc[3][1], a23.y, b01.y);
            fma2(acc[3][2], a23.y, b23.x); fma2(acc[3][3], a23.y, b23.y);
        }
        __syncthreads();
    }

    float bv[8];
#pragma unroll
    for (int j = 0; j < 8; j++) bv[j] = bias[h0 + tn * 8 + j];
#pragma unroll
    for (int i = 0; i < 4; i++) {
        int r  = r0 + tm * 4 + i;
        int bb = r >> 9;
        int tt = r & 511;
        float* orow = g_xproj + (((size_t)g * T_ + tt) * B_ + bb) * H_ + h0 + tn * 8;
#pragma unroll
        for (int jp = 0; jp < 4; jp++) {
            float2 v = make_float2(lo32(acc[i][jp]) + bv[jp * 2],
                                   hi32(acc[i][jp]) + bv[jp * 2 + 1]);
            *(float2*)(orow + jp * 2) = v;
        }
    }
}

// ---------------------------------------------------------------------------
// global spin barrier (sense = monotone generation; reset each replay)
// ---------------------------------------------------------------------------
__device__ __forceinline__ void gbar(unsigned gen) {
    if (threadIdx.x == 0) {
        __threadfence();
        unsigned arr = atomicAdd(&g_count, 1u);
        if (arr == NCTA - 1) {
            g_count = 0;
            __threadfence();
            asm volatile("st.release.gpu.u32 [%0], %1;"
                         :: "l"(&g_sense), "r"(gen) : "memory");
        } else {
            unsigned v;
            do {
                asm volatile("ld.acquire.gpu.u32 %0, [%1];"
                             : "=r"(v) : "l"(&g_sense) : "memory");
            } while (v != gen);
        }
    }
    __syncthreads();
}

// ---------------------------------------------------------------------------
// persistent recurrence: 128 CTAs x 256 threads, all 512 steps in one launch.
// CTA tile: M=64 gate-rows (4 gates x 16 h), N=32 batch, K=512.
// R tile (128KB) resident in smem the whole kernel. c & h-sum in registers.
// Micro per thread: 2M x 4N via f32x2 packed over N.
// ---------------------------------------------------------------------------
__global__ __launch_bounds__(256, 1) void lstm_recur(
    const float* __restrict__ Rz, const float* __restrict__ Rs_,
    const float* __restrict__ Rf, const float* __restrict__ Ro,
    float* __restrict__ out)
{
    extern __shared__ float sm[];
    float* Rsm = sm;                               // [512][64]  128KB
    float* Hs  = sm + 512 * 64;                    // [2][64*32]  16KB
    float* act = sm + 512 * 64 + 2 * 64 * 32;      // [32][68]    8.5KB

    const int tid = threadIdx.x;
    const int cta = blockIdx.x;
    const int h0  = (cta >> 2) * 16;   // 32 h-tiles
    const int b0  = (cta & 3) * 32;    // 4 b-tiles

    const int tn  = tid & 7;           // N micro: n = tn*4
    const int tm  = tid >> 3;          // M micro: m = tm*2 (0..31 -> M 0..63)
    const int gg  = tm >> 3;           // gate of this thread's rows (uniform per warp)
    const int hr  = (tm * 2) & 15;     // h-row within tile (hr, hr+1)

    // ---- load R tile into smem once: Rsm[k][m], m = g*16+h ----
    {
        int m  = tid >> 2;
        int ks = (tid & 3) * 128;
        int rg = m >> 4, hh = m & 15;
        const float* Rp = ((rg == 0) ? Rz : (rg == 1) ? Rs_ : (rg == 2) ? Rf : Ro)
                        + (size_t)(h0 + hh) * H_ + ks;
        for (int j = 0; j < 128; j += 4) {
            float4 v = *(const float4*)(Rp + j);
            int k = ks + j;
            Rsm[(k + 0) * 64 + m] = v.x;
            Rsm[(k + 1) * 64 + m] = v.y;
            Rsm[(k + 2) * 64 + m] = v.z;
            Rsm[(k + 3) * 64 + m] = v.w;
        }
    }
    __syncthreads();

    // combine-phase identity: this thread owns (bl, hh), (bl, hh+1) forever
    const int cp  = tid * 2;
    const int cbl = cp >> 4;
    const int chh = cp & 15;           // even
    float creg0 = 0.0f, creg1 = 0.0f;  // cell state (registers)
    float hsum0 = 0.0f, hsum1 = 0.0f;  // running sum of h

    const int hb = tid & 31;           // h staging: batch lane
    const int hk = (tid >> 5) * 8;     // h staging: k octet

    for (int t = 0; t < T_; t++) {
        // prefetch this thread's xproj values (consumed in epilogue, ~8k cyc later)
        float2 xpv[4];
        {
            const float* xb = g_xproj + ((size_t)gg * T_ + t) * B_ * H_ + h0 + hr;
#pragma unroll
            for (int b = 0; b < 4; b++)
                xpv[b] = *(const float2*)(xb + (size_t)(b0 + tn * 4 + b) * H_);
        }

        unsigned long long acc00 = 0, acc01 = 0, acc10 = 0, acc11 = 0;

        if (t > 0) {
            const float* hp = g_h[t & 1] + (size_t)(b0 + hb) * H_;
            float4 h0r = *(const float4*)(hp + hk);
            float4 h1r = *(const float4*)(hp + hk + 4);
            for (int kt = 0; kt < 8; kt++) {
                float* Hb = Hs + (kt & 1) * (64 * 32);
                Hb[(hk + 0) * 32 + hb] = h0r.x;
                Hb[(hk + 1) * 32 + hb] = h0r.y;
                Hb[(hk + 2) * 32 + hb] = h0r.z;
                Hb[(hk + 3) * 32 + hb] = h0r.w;
                Hb[(hk + 4) * 32 + hb] = h1r.x;
                Hb[(hk + 5) * 32 + hb] = h1r.y;
                Hb[(hk + 6) * 32 + hb] = h1r.z;
                Hb[(hk + 7) * 32 + hb] = h1r.w;
                if (kt < 7) {   // issue next-tile loads before the barrier
                    h0r = *(const float4*)(hp + (kt + 1) * 64 + hk);
                    h1r = *(const float4*)(hp + (kt + 1) * 64 + hk + 4);
                }
                __syncthreads();
                const float* Rk = Rsm + (kt * 64) * 64 + tm * 2;
                const float* Hk = Hb + tn * 4;
#pragma unroll 16
                for (int kk = 0; kk < 64; kk++) {
                    uint2 ar = *(const uint2*)(Rk + kk * 64);
                    unsigned long long a0 = dup32(ar.x);
                    unsigned long long a1 = dup32(ar.y);
                    ulonglong2 bv = *(const ulonglong2*)(Hk + kk * 32);
                    fma2(acc00, a0, bv.x); fma2(acc01, a0, bv.y);
                    fma2(acc10, a1, bv.x); fma2(acc11, a1, bv.y);
                }
                __syncthreads();
            }
        }

        // epilogue: pre-activation + nonlinearity -> act[bl][hr*4+g]
        {
            float p0[4], p1[4];
            p0[0] = lo32(acc00) + xpv[0].x;  p0[1] = hi32(acc00) + xpv[1].x;
            p0[2] = lo32(acc01) + xpv[2].x;  p0[3] = hi32(acc01) + xpv[3].x;
            p1[0] = lo32(acc10) + xpv[0].y;  p1[1] = hi32(acc10) + xpv[1].y;
            p1[2] = lo32(acc11) + xpv[2].y;  p1[3] = hi32(acc11) + xpv[3].y;
            if (gg == 0) {
#pragma unroll
                for (int b = 0; b < 4; b++) { p0[b] = tanhf(p0[b]); p1[b] = tanhf(p1[b]); }
            } else {
#pragma unroll
                for (int b = 0; b < 4; b++) { p0[b] = sigmoidf_(p0[b]); p1[b] = sigmoidf_(p1[b]); }
            }
#pragma unroll
            for (int b = 0; b < 4; b++) {
                int bl = tn * 4 + b;
                act[bl * 68 + (hr + 0) * 4 + gg] = p0[b];
                act[bl * 68 + (hr + 1) * 4 + gg] = p1[b];
            }
        }
        __syncthreads();

        // combine: z,s,f,o -> c,h update; h_new to global; hsum in regs
        {
            float4 a0v = *(const float4*)&act[cbl * 68 + (chh + 0) * 4];
            float4 a1v = *(const float4*)&act[cbl * 68 + (chh + 1) * 4];
            float c0 = a0v.y * a0v.x + a0v.z * creg0;   // s*z + f*c
            float c1 = a1v.y * a1v.x + a1v.z * creg1;
            creg0 = c0; creg1 = c1;
            float hn0 = a0v.w * tanhf(c0);
            float hn1 = a1v.w * tanhf(c1);
            hsum0 += hn0; hsum1 += hn1;
            float* hw = g_h[(t + 1) & 1] + (size_t)(b0 + cbl) * H_ + h0 + chh;
            *(float2*)hw = make_float2(hn0, hn1);
        }

        if (t < T_ - 1) {
            gbar((unsigned)(t + 1));   // includes __syncthreads (protects act reuse)
        } else {
            float* ow = out + (size_t)(b0 + cbl) * H_ + h0 + chh;
            *(float2*)ow = make_float2(hsum0 * (1.0f / (float)T_),
                                       hsum1 * (1.0f / (float)T_));
        }
    }
}

// ---------------------------------------------------------------------------
extern "C" void kernel_launch(void* const* d_in, const int* in_sizes, int n_in,
                              void* d_out, int out_size) {
    const float* x  = (const float*)d_in[0];
    const float* Wz = (const float*)d_in[1];
    const float* Ws = (const float*)d_in[2];
    const float* Wf = (const float*)d_in[3];
    const float* Wo = (const float*)d_in[4];
    const float* Rz = (const float*)d_in[5];
    const float* Rs = (const float*)d_in[6];
    const float* Rf = (const float*)d_in[7];
    const float* Ro = (const float*)d_in[8];
    const float* bz = (const float*)d_in[9];
    const float* bs = (const float*)d_in[10];
    const float* bf = (const float*)d_in[11];
    const float* bo = (const float*)d_in[12];

    const int smem_bytes = (512 * 64 + 2 * 64 * 32 + 32 * 68) * 4;  // 156160
    cudaFuncSetAttribute(lstm_recur,
                         cudaFuncAttributeMaxDynamicSharedMemorySize, smem_bytes);

    lstm_reset<<<1, 32>>>();
    lstm_proj<<<dim3((B_ * T_) / 64, (4 * H_) / 64), 128>>>(
        x, Wz, Ws, Wf, Wo, bz, bs, bf, bo);
    lstm_recur<<<NCTA, 256, smem_bytes>>>(Rz, Rs, Rf, Ro, (float*)d_out);
}